// round 1
// baseline (speedup 1.0000x reference)
#include <cuda_runtime.h>
#include <math.h>
#include <stdint.h>

// ---------------- problem constants ----------------
#define Bc   32
#define NRc  4096
#define DIN  384
#define DCTX 128
#define Hc   64
#define Ac   16
#define MTOT (Bc * NRc)   // 131072 rows

#define LOG_VAR2_C  (-4.6051701859880914f)  // ln(0.01)
#define INV_VAR2_C  (100.0f)                // 1/0.01
#define STD2_C      (0.1f)

// ---------------- device scratch (no allocs allowed) ----------------
// emb transposed: [b][k][n]  (k = H dim, n = role index) -> coalesced matvec in scan
__device__ float g_embT[(size_t)Bc * Hc * NRc];   // 33.5 MB
__device__ float g_mse[Bc];
__device__ float g_kld[Bc];

// ---------------- zero accumulators ----------------
__global__ void zero_kernel() {
    int t = threadIdx.x;
    if (t < Bc) { g_mse[t] = 0.0f; g_kld[t] = 0.0f; }
}

// ---------------- fused VAE kernel ----------------
// grid = MTOT/128 blocks, 256 threads. Each block owns 128 consecutive rows
// (never straddles a batch item since 128 | 4096).
//
// smem layout (floats):
//   As : 16*128   (roles K-tile, [k][m])
//   Bs : 16*64    (W1 K-tile,   [k][j])
//   Hs : 128*65   (h, then z, then g)   padded stride 65
//   Ws : 64*64    (W22 / W21 / W3 / W4-chunk)
//   red: 64       (block reduction)
//   rns: 128      (per-row inv-norms)
#define VAE_SMEM_FLOATS (16*128 + 16*64 + 128*65 + 64*64 + 64 + 128)

__global__ __launch_bounds__(256, 2)
void vae_kernel(const float* __restrict__ roles, const float* __restrict__ eps,
                const float* __restrict__ W1,  const float* __restrict__ b1,
                const float* __restrict__ W21, const float* __restrict__ b21,
                const float* __restrict__ W22, const float* __restrict__ b22,
                const float* __restrict__ W3,  const float* __restrict__ b3,
                const float* __restrict__ W4,  const float* __restrict__ b4)
{
    extern __shared__ float sm[];
    float* As  = sm;                 // 2048
    float* Bs  = As + 16*128;        // 1024
    float* Hs  = Bs + 16*64;         // 8320
    float* Ws  = Hs + 128*65;        // 4096
    float* red = Ws + 64*64;         // 64
    float* rns = red + 64;           // 128

    const int tid  = threadIdx.x;
    const int tcol = tid & 15;       // 16 col groups * 4 cols
    const int trow = tid >> 4;       // 16 row groups * 8 rows
    const int row0 = blockIdx.x * 128;
    const int b    = row0 >> 12;     // /4096

    float acc[8][4];

    // ================= GEMM1: h = relu(roles @ W1 + b1) =================
#pragma unroll
    for (int i = 0; i < 8; i++)
#pragma unroll
        for (int j = 0; j < 4; j++) acc[i][j] = 0.0f;

    for (int kt = 0; kt < DIN; kt += 16) {
        // load A tile (128 x 16) transposed into As[k][m]
#pragma unroll
        for (int q = 0; q < 2; q++) {
            int f  = tid + q * 256;      // 0..511 float4 slots
            int m  = f >> 2;
            int k4 = (f & 3) * 4;
            float4 v = *reinterpret_cast<const float4*>(
                roles + (size_t)(row0 + m) * DIN + kt + k4);
            As[(k4 + 0) * 128 + m] = v.x;
            As[(k4 + 1) * 128 + m] = v.y;
            As[(k4 + 2) * 128 + m] = v.z;
            As[(k4 + 3) * 128 + m] = v.w;
        }
        // load B tile (16 x 64)
        {
            int k  = tid >> 4;
            int j4 = (tid & 15) * 4;
            *reinterpret_cast<float4*>(&Bs[k * 64 + j4]) =
                *reinterpret_cast<const float4*>(W1 + (size_t)(kt + k) * Hc + j4);
        }
        __syncthreads();
#pragma unroll
        for (int k = 0; k < 16; k++) {
            float a[8];
            *reinterpret_cast<float4*>(&a[0]) = *reinterpret_cast<float4*>(&As[k*128 + trow*8]);
            *reinterpret_cast<float4*>(&a[4]) = *reinterpret_cast<float4*>(&As[k*128 + trow*8 + 4]);
            float4 bb = *reinterpret_cast<float4*>(&Bs[k*64 + tcol*4]);
#pragma unroll
            for (int i = 0; i < 8; i++) {
                acc[i][0] += a[i] * bb.x;
                acc[i][1] += a[i] * bb.y;
                acc[i][2] += a[i] * bb.z;
                acc[i][3] += a[i] * bb.w;
            }
        }
        __syncthreads();
    }
    // epilogue: relu(+b1) -> Hs
    {
        float4 bv = *reinterpret_cast<const float4*>(b1 + tcol * 4);
#pragma unroll
        for (int i = 0; i < 8; i++) {
            int r = trow * 8 + i;
            Hs[r*65 + tcol*4 + 0] = fmaxf(acc[i][0] + bv.x, 0.0f);
            Hs[r*65 + tcol*4 + 1] = fmaxf(acc[i][1] + bv.y, 0.0f);
            Hs[r*65 + tcol*4 + 2] = fmaxf(acc[i][2] + bv.z, 0.0f);
            Hs[r*65 + tcol*4 + 3] = fmaxf(acc[i][3] + bv.w, 0.0f);
        }
    }
    // load W22
    for (int t = tid; t < 1024; t += 256)
        *reinterpret_cast<float4*>(&Ws[t*4]) = *reinterpret_cast<const float4*>(W22 + t*4);
    __syncthreads();

    float kacc = 0.0f;
    float sreg[8][4];

    // ================= log_var = h@W22 + b22 ; s = exp(0.5 lv)*STD2 =================
#pragma unroll
    for (int i = 0; i < 8; i++)
#pragma unroll
        for (int j = 0; j < 4; j++) acc[i][j] = 0.0f;
#pragma unroll 8
    for (int k = 0; k < 64; k++) {
        float a[8];
#pragma unroll
        for (int i = 0; i < 8; i++) a[i] = Hs[(trow*8 + i)*65 + k];
        float4 bb = *reinterpret_cast<float4*>(&Ws[k*64 + tcol*4]);
#pragma unroll
        for (int i = 0; i < 8; i++) {
            acc[i][0] += a[i]*bb.x; acc[i][1] += a[i]*bb.y;
            acc[i][2] += a[i]*bb.z; acc[i][3] += a[i]*bb.w;
        }
    }
    {
        float4 bv = *reinterpret_cast<const float4*>(b22 + tcol * 4);
#pragma unroll
        for (int i = 0; i < 8; i++) {
            float bvv[4] = {bv.x, bv.y, bv.z, bv.w};
#pragma unroll
            for (int j = 0; j < 4; j++) {
                float lv = acc[i][j] + bvv[j];
                float ex = expf(lv);
                kacc += (1.0f - LOG_VAR2_C + lv - ex * INV_VAR2_C);
                sreg[i][j] = expf(0.5f * lv) * STD2_C;
            }
        }
    }
    __syncthreads();
    // load W21
    for (int t = tid; t < 1024; t += 256)
        *reinterpret_cast<float4*>(&Ws[t*4]) = *reinterpret_cast<const float4*>(W21 + t*4);
    __syncthreads();

    // ================= mu = h@W21 + b21 ; z = mu + eps*s =================
#pragma unroll
    for (int i = 0; i < 8; i++)
#pragma unroll
        for (int j = 0; j < 4; j++) acc[i][j] = 0.0f;
#pragma unroll 8
    for (int k = 0; k < 64; k++) {
        float a[8];
#pragma unroll
        for (int i = 0; i < 8; i++) a[i] = Hs[(trow*8 + i)*65 + k];
        float4 bb = *reinterpret_cast<float4*>(&Ws[k*64 + tcol*4]);
#pragma unroll
        for (int i = 0; i < 8; i++) {
            acc[i][0] += a[i]*bb.x; acc[i][1] += a[i]*bb.y;
            acc[i][2] += a[i]*bb.z; acc[i][3] += a[i]*bb.w;
        }
    }
    {
        float4 bv = *reinterpret_cast<const float4*>(b21 + tcol * 4);
        float bvv[4] = {bv.x, bv.y, bv.z, bv.w};
#pragma unroll
        for (int i = 0; i < 8; i++) {
            float4 ev = *reinterpret_cast<const float4*>(
                eps + (size_t)(row0 + trow*8 + i) * Hc + tcol * 4);
            float evv[4] = {ev.x, ev.y, ev.z, ev.w};
#pragma unroll
            for (int j = 0; j < 4; j++) {
                float mu = acc[i][j] + bvv[j];
                kacc -= mu * mu * INV_VAR2_C;
                acc[i][j] = mu + evv[j] * sreg[i][j];   // z
            }
        }
    }
    __syncthreads();                 // all reads of Hs(h) done
    // Hs = z ; load W3
#pragma unroll
    for (int i = 0; i < 8; i++) {
        int r = trow * 8 + i;
        Hs[r*65 + tcol*4 + 0] = acc[i][0];
        Hs[r*65 + tcol*4 + 1] = acc[i][1];
        Hs[r*65 + tcol*4 + 2] = acc[i][2];
        Hs[r*65 + tcol*4 + 3] = acc[i][3];
    }
    for (int t = tid; t < 1024; t += 256)
        *reinterpret_cast<float4*>(&Ws[t*4]) = *reinterpret_cast<const float4*>(W3 + t*4);
    __syncthreads();

    // ================= role_emb = l2norm(z), stored transposed =================
    if (tid < 128) {
        float ss = 0.0f;
#pragma unroll
        for (int k = 0; k < 64; k++) { float v = Hs[tid*65 + k]; ss += v * v; }
        rns[tid] = 1.0f / fmaxf(sqrtf(ss), 1e-12f);
    }
    __syncthreads();
    {
        const int nloc0 = row0 & (NRc - 1);
        for (int t = tid; t < 128 * 64; t += 256) {
            int k = t >> 7;
            int r = t & 127;
            g_embT[((size_t)b * Hc + k) * NRc + nloc0 + r] = Hs[r*65 + k] * rns[r];
        }
    }

    // ================= g = relu(z@W3 + b3) =================
#pragma unroll
    for (int i = 0; i < 8; i++)
#pragma unroll
        for (int j = 0; j < 4; j++) acc[i][j] = 0.0f;
#pragma unroll 8
    for (int k = 0; k < 64; k++) {
        float a[8];
#pragma unroll
        for (int i = 0; i < 8; i++) a[i] = Hs[(trow*8 + i)*65 + k];
        float4 bb = *reinterpret_cast<float4*>(&Ws[k*64 + tcol*4]);
#pragma unroll
        for (int i = 0; i < 8; i++) {
            acc[i][0] += a[i]*bb.x; acc[i][1] += a[i]*bb.y;
            acc[i][2] += a[i]*bb.z; acc[i][3] += a[i]*bb.w;
        }
    }
    {
        float4 bv = *reinterpret_cast<const float4*>(b3 + tcol * 4);
        float bvv[4] = {bv.x, bv.y, bv.z, bv.w};
#pragma unroll
        for (int i = 0; i < 8; i++)
#pragma unroll
            for (int j = 0; j < 4; j++)
                acc[i][j] = fmaxf(acc[i][j] + bvv[j], 0.0f);
    }
    __syncthreads();                 // all reads of Hs(z) and Ws(W3) done
    // Hs = g
#pragma unroll
    for (int i = 0; i < 8; i++) {
        int r = trow * 8 + i;
        Hs[r*65 + tcol*4 + 0] = acc[i][0];
        Hs[r*65 + tcol*4 + 1] = acc[i][1];
        Hs[r*65 + tcol*4 + 2] = acc[i][2];
        Hs[r*65 + tcol*4 + 3] = acc[i][3];
    }

    // ================= mse: x_hat = g@W4 + b4 vs roles, 6 col-chunks =================
    float msacc = 0.0f;
    for (int ch = 0; ch < 6; ch++) {
        for (int t = tid; t < 1024; t += 256) {
            int k  = t >> 4;
            int j4 = (t & 15) * 4;
            *reinterpret_cast<float4*>(&Ws[k*64 + j4]) =
                *reinterpret_cast<const float4*>(W4 + (size_t)k * DIN + ch * 64 + j4);
        }
        __syncthreads();
#pragma unroll
        for (int i = 0; i < 8; i++)
#pragma unroll
            for (int j = 0; j < 4; j++) acc[i][j] = 0.0f;
#pragma unroll 8
        for (int k = 0; k < 64; k++) {
            float a[8];
#pragma unroll
            for (int i = 0; i < 8; i++) a[i] = Hs[(trow*8 + i)*65 + k];
            float4 bb = *reinterpret_cast<float4*>(&Ws[k*64 + tcol*4]);
#pragma unroll
            for (int i = 0; i < 8; i++) {
                acc[i][0] += a[i]*bb.x; acc[i][1] += a[i]*bb.y;
                acc[i][2] += a[i]*bb.z; acc[i][3] += a[i]*bb.w;
            }
        }
        {
            float4 bv = *reinterpret_cast<const float4*>(b4 + ch * 64 + tcol * 4);
            float bvv[4] = {bv.x, bv.y, bv.z, bv.w};
#pragma unroll
            for (int i = 0; i < 8; i++) {
                float4 rv = *reinterpret_cast<const float4*>(
                    roles + (size_t)(row0 + trow*8 + i) * DIN + ch * 64 + tcol * 4);
                float rvv[4] = {rv.x, rv.y, rv.z, rv.w};
#pragma unroll
                for (int j = 0; j < 4; j++) {
                    float d = acc[i][j] + bvv[j] - rvv[j];
                    msacc += d * d;
                }
            }
        }
        __syncthreads();
    }

    // ================= block reduce kld / mse =================
    float ks = kacc, ms = msacc;
#pragma unroll
    for (int off = 16; off > 0; off >>= 1) {
        ks += __shfl_xor_sync(0xffffffffu, ks, off);
        ms += __shfl_xor_sync(0xffffffffu, ms, off);
    }
    if ((tid & 31) == 0) { red[tid >> 5] = ks; red[8 + (tid >> 5)] = ms; }
    __syncthreads();
    if (tid == 0) {
        float kt = 0.0f, mt = 0.0f;
#pragma unroll
        for (int w = 0; w < 8; w++) { kt += red[w]; mt += red[8 + w]; }
        atomicAdd(&g_kld[b], kt);
        atomicAdd(&g_mse[b], mt);
    }
}

// ---------------- vae loss finalize ----------------
__global__ void finalize_kernel(float* __restrict__ out) {
    if (threadIdx.x == 0) {
        float v = 0.0f;
        for (int b = 0; b < Bc; b++) {
            float mse = g_mse[b] * (1.0f / ((float)NRc * (float)DIN));
            float kld = (-0.5f / ((float)NRc * (float)Hc)) * g_kld[b];
            v += mse + kld;
        }
        out[Bc*Ac + Bc + Bc*Hc] = v / (float)Bc;   // out[2592]
    }
}

// ---------------- sequential selection scan ----------------
// 1 block per batch item, 1024 threads; thread t owns rows 4t..4t+3.
#define SCAN_SMEM_FLOATS (192*64 + 128 + 64 + 64 + 64 + 64 + 32 + 32 + 8 + 4)

__global__ __launch_bounds__(1024, 1)
void scan_kernel(const float* __restrict__ contexts, const float* __restrict__ rand_vals,
                 const float* __restrict__ Wc, const float* __restrict__ bc,
                 const float* __restrict__ init_emb, float* __restrict__ out)
{
    extern __shared__ float sm[];
    float* Wcs  = sm;               // 12288
    float* ctxs = Wcs + 192*64;     // 128
    float* hist = ctxs + 128;       // 64
    float* cur  = hist + 64;        // 64
    float* tmp  = cur + 64;         // 64
    float* cvec = tmp + 64;         // 64
    float* wred = cvec + 64;        // 32
    float* wred2= wred + 32;        // 32
    float* scal = wred2 + 32;       // 8: [0]=mean [1]=invstd [2]=cnorm [3]=gmax [4]=lp [5]=S [6]=lpAdd
    int*   seli = (int*)(scal + 8);

    const int b    = blockIdx.x;
    const int tid  = threadIdx.x;
    const int lane = tid & 31;
    const int wid  = tid >> 5;
    const float* embT = g_embT + (size_t)b * Hc * NRc;

    for (int t = tid; t < 192*64/4; t += 1024)
        *reinterpret_cast<float4*>(&Wcs[t*4]) = *reinterpret_cast<const float4*>(Wc + t*4);
    if (tid < 128) ctxs[tid] = contexts[b * DCTX + tid];
    if (tid < 64)  { float iv = init_emb[tid]; hist[tid] = iv; cur[tid] = iv; }
    if (tid == 0)  scal[4] = 0.0f;
    __syncthreads();

    for (int step = 0; step < Ac; step++) {
        // ---- hist = layernorm(hist + cur)
        if (tid < 64) tmp[tid] = hist[tid] + cur[tid];
        if (tid == 0) seli[0] = 0x7fffffff;
        __syncthreads();
        if (wid == 0) {
            float x0 = tmp[lane], x1 = tmp[lane + 32];
            float s = x0 + x1;
#pragma unroll
            for (int off = 16; off > 0; off >>= 1) s += __shfl_xor_sync(0xffffffffu, s, off);
            float mean = s * (1.0f / 64.0f);
            float d0 = x0 - mean, d1 = x1 - mean;
            float vs = d0*d0 + d1*d1;
#pragma unroll
            for (int off = 16; off > 0; off >>= 1) vs += __shfl_xor_sync(0xffffffffu, vs, off);
            if (lane == 0) {
                scal[0] = mean;
                scal[1] = 1.0f / sqrtf(vs * (1.0f / 64.0f) + 1e-5f);
            }
        }
        __syncthreads();
        if (tid < 64) hist[tid] = (tmp[tid] - scal[0]) * scal[1];
        __syncthreads();

        // ---- c = concat(ctx, hist) @ Wc + bc, then normalize
        if (tid < 64) {
            float c = bc[tid];
#pragma unroll 4
            for (int i = 0; i < 128; i++) c += ctxs[i] * Wcs[i*64 + tid];
#pragma unroll 4
            for (int i = 0; i < 64; i++)  c += hist[i] * Wcs[(128 + i)*64 + tid];
            cvec[tid] = c;
        }
        __syncthreads();
        if (wid == 0) {
            float c0 = cvec[lane], c1 = cvec[lane + 32];
            float ss = c0*c0 + c1*c1;
#pragma unroll
            for (int off = 16; off > 0; off >>= 1) ss += __shfl_xor_sync(0xffffffffu, ss, off);
            if (lane == 0) scal[2] = 1.0f / fmaxf(sqrtf(ss), 1e-12f);
        }
        __syncthreads();
        if (tid < 64) cvec[tid] *= scal[2];
        __syncthreads();

        // ---- scores = softmax(emb @ c)
        const float* ebase = embT + 4 * tid;
        float sx = 0.f, sy = 0.f, sz = 0.f, sw = 0.f;
#pragma unroll 8
        for (int k = 0; k < 64; k++) {
            float4 v = *reinterpret_cast<const float4*>(ebase + (size_t)k * NRc);
            float ck = cvec[k];
            sx += v.x * ck; sy += v.y * ck; sz += v.z * ck; sw += v.w * ck;
        }
        // block max
        float m = fmaxf(fmaxf(sx, sy), fmaxf(sz, sw));
#pragma unroll
        for (int off = 16; off > 0; off >>= 1) m = fmaxf(m, __shfl_xor_sync(0xffffffffu, m, off));
        if (lane == 0) wred[wid] = m;
        __syncthreads();
        if (wid == 0) {
            float mm = wred[lane];
#pragma unroll
            for (int off = 16; off > 0; off >>= 1) mm = fmaxf(mm, __shfl_xor_sync(0xffffffffu, mm, off));
            if (lane == 0) scal[3] = mm;
        }
        __syncthreads();
        float gmax = scal[3];
        float e0 = expf(sx - gmax), e1 = expf(sy - gmax),
              e2 = expf(sz - gmax), e3 = expf(sw - gmax);
        float tsum = (e0 + e1) + (e2 + e3);
        float ts = tsum;
#pragma unroll
        for (int off = 16; off > 0; off >>= 1) ts += __shfl_xor_sync(0xffffffffu, ts, off);
        if (lane == 0) wred[wid] = ts;
        __syncthreads();
        if (wid == 0) {
            float ss = wred[lane];
#pragma unroll
            for (int off = 16; off > 0; off >>= 1) ss += __shfl_xor_sync(0xffffffffu, ss, off);
            if (lane == 0) scal[5] = ss;
        }
        __syncthreads();
        float Sinv = 1.0f / scal[5];
        float p0 = e0 * Sinv, p1 = e1 * Sinv, p2 = e2 * Sinv, p3 = e3 * Sinv;
        float q0 = p0, q1 = q0 + p1, q2 = q1 + p2, q3 = q2 + p3;

        // ---- block-exclusive scan of per-thread totals (row order == tid order)
        float incl = q3;
#pragma unroll
        for (int off = 1; off < 32; off <<= 1) {
            float n = __shfl_up_sync(0xffffffffu, incl, off);
            if (lane >= off) incl += n;
        }
        if (lane == 31) wred2[wid] = incl;
        __syncthreads();
        if (wid == 0) {
            float v = wred2[lane];
            float i2 = v;
#pragma unroll
            for (int off = 1; off < 32; off <<= 1) {
                float n = __shfl_up_sync(0xffffffffu, i2, off);
                if (lane >= off) i2 += n;
            }
            wred2[lane] = i2 - v;   // exclusive warp offset
        }
        __syncthreads();
        float excl = wred2[wid] + (incl - q3);

        float r = rand_vals[b * Ac + step];
        int cand = 0x7fffffff;
        if      (excl + q0 > r) cand = tid * 4;
        else if (excl + q1 > r) cand = tid * 4 + 1;
        else if (excl + q2 > r) cand = tid * 4 + 2;
        else if (excl + q3 > r) cand = tid * 4 + 3;
        if (cand != 0x7fffffff) atomicMin(seli, cand);
        __syncthreads();
        int sel = seli[0];
        if (sel == 0x7fffffff) sel = 0;   // argmax of all-False -> 0

        if (sel >= tid * 4 && sel < tid * 4 + 4) {
            float ps = (sel == tid*4) ? p0 : (sel == tid*4+1) ? p1 : (sel == tid*4+2) ? p2 : p3;
            scal[6] = logf(ps);
        }
        __syncthreads();
        if (tid == 0) {
            scal[4] += scal[6];
            out[b * Ac + step] = (float)sel;
        }
        if (tid < 64) cur[tid] = embT[(size_t)tid * NRc + sel];
        __syncthreads();
    }

    if (tid == 0) out[Bc*Ac + b] = scal[4];                         // log_probs
    if (tid < 64) out[Bc*Ac + Bc + b*Hc + tid] = hist[tid];         // summary_role
}

// ---------------- launcher ----------------
extern "C" void kernel_launch(void* const* d_in, const int* in_sizes, int n_in,
                              void* d_out, int out_size) {
    const float* roles     = (const float*)d_in[0];
    const float* contexts  = (const float*)d_in[1];
    const float* eps       = (const float*)d_in[2];
    const float* rand_vals = (const float*)d_in[3];
    // d_in[4] = agent_num (scalar, fixed at 16)
    const float* W1  = (const float*)d_in[5];
    const float* b1  = (const float*)d_in[6];
    const float* W21 = (const float*)d_in[7];
    const float* b21 = (const float*)d_in[8];
    const float* W22 = (const float*)d_in[9];
    const float* b22 = (const float*)d_in[10];
    const float* W3  = (const float*)d_in[11];
    const float* b3  = (const float*)d_in[12];
    const float* W4  = (const float*)d_in[13];
    const float* b4  = (const float*)d_in[14];
    const float* Wc  = (const float*)d_in[15];
    const float* bc  = (const float*)d_in[16];
    const float* init_emb = (const float*)d_in[17];
    float* out = (float*)d_out;

    const int vae_smem  = VAE_SMEM_FLOATS  * (int)sizeof(float);
    const int scan_smem = SCAN_SMEM_FLOATS * (int)sizeof(float);
    cudaFuncSetAttribute(vae_kernel,  cudaFuncAttributeMaxDynamicSharedMemorySize, vae_smem);
    cudaFuncSetAttribute(scan_kernel, cudaFuncAttributeMaxDynamicSharedMemorySize, scan_smem);

    zero_kernel<<<1, 32>>>();
    vae_kernel<<<MTOT / 128, 256, vae_smem>>>(roles, eps, W1, b1, W21, b21,
                                              W22, b22, W3, b3, W4, b4);
    finalize_kernel<<<1, 1>>>(out);
    scan_kernel<<<Bc, 1024, scan_smem>>>(contexts, rand_vals, Wc, bc, init_emb, out);
}